// round 2
// baseline (speedup 1.0000x reference)
#include <cuda_runtime.h>
#include <stdint.h>

// ---------------------------------------------------------------------------
// MultiHeadAttention: out = LN(ctx@W_fc + X@W_fc0), attn materialized.
// B=8, S=2048, D=128, H=4, dk=dv=32.
// Output buffer layout: [out (8*2048*128)] then [attn (8*4*2048*2048)].
// ---------------------------------------------------------------------------

namespace {
constexpr int BATCH = 8;
constexpr int SEQ   = 2048;
constexpr int DM    = 128;
constexpr int NH    = 4;
constexpr int DKC   = 32;
constexpr int NR    = BATCH * SEQ;                 // 16384 rows
constexpr size_t OUT_ELEMS = (size_t)NR * DM;      // 2,097,152
constexpr int TQ = 128;                            // q-tile per block
constexpr int TK = 64;                             // k-chunk
// dynamic smem layout for attn kernel (floats)
constexpr int SQT_OFF = 0;                 // sQt[32][132]
constexpr int SKT_OFF = 32 * 132;          // sKt[32][68]
constexpr int SVT_OFF = SKT_OFF + 32 * 68; // sVt[32][68]
constexpr int SS_OFF  = SVT_OFF + 32 * 68; // sS [128][68]
constexpr int SMEM_FLOATS = SS_OFF + 128 * 68;
constexpr size_t SMEM_BYTES = (size_t)SMEM_FLOATS * 4;  // 69,120 B
}

// Scratch (device globals: allocation-free rule)
__device__ float g_R  [NR * DM];
__device__ float g_Qp [NR * DM];
__device__ float g_Kp [NR * DM];
__device__ float g_Vp [NR * DM];
__device__ float g_ctx[NR * DM];
__device__ float g_rinv[BATCH * NH * SEQ];
__device__ int   g_mask_mode;   // 0=uint8, 1=int32, 2=float32

// ---------------------------------------------------------------------------
// K0: detect mask dtype from byte patterns in the first 4096 bytes.
//  - float32 1.0f has bytes {0,0,0x80,0x3f} -> bytes > 1 present
//  - uint8 mask has value-1 bytes at arbitrary offsets (incl. %4 != 0)
//  - int32 mask has value-1 bytes ONLY at offsets %4 == 0
// ---------------------------------------------------------------------------
__global__ void detect_mask(const unsigned char* __restrict__ m)
{
    __shared__ int s_gt1, s_off;
    if (threadIdx.x == 0) { s_gt1 = 0; s_off = 0; }
    __syncthreads();
    int gt1 = 0, off = 0;
    for (int i = threadIdx.x; i < 4096; i += 256) {
        unsigned char v = m[i];
        if (v > 1) gt1 = 1;
        else if (v == 1 && (i & 3) != 0) off = 1;
    }
    if (gt1) atomicOr(&s_gt1, 1);
    if (off) atomicOr(&s_off, 1);
    __syncthreads();
    if (threadIdx.x == 0)
        g_mask_mode = s_gt1 ? 2 : (s_off ? 0 : 1);
}

// Load 4 consecutive mask flags starting at element index idx (16B aligned
// for 4-byte modes since idx % 4 == 0 by construction).
__device__ __forceinline__ uint4 load_mask4(const unsigned char* __restrict__ mask,
                                            size_t idx, int mode)
{
    if (mode == 0) {
        uchar4 m = *(const uchar4*)(mask + idx);
        return make_uint4(m.x, m.y, m.z, m.w);
    } else if (mode == 1) {
        int4 m = *(const int4*)((const int*)mask + idx);
        return make_uint4((unsigned)m.x, (unsigned)m.y, (unsigned)m.z, (unsigned)m.w);
    } else {
        float4 m = *(const float4*)((const float*)mask + idx);
        return make_uint4(m.x != 0.f, m.y != 0.f, m.z != 0.f, m.w != 0.f);
    }
}

// ---------------------------------------------------------------------------
// K1: C[16384,128] = A[16384,128] @ W[128,128]
// ---------------------------------------------------------------------------
__global__ __launch_bounds__(256) void gemm_proj(const float* __restrict__ A,
                                                 const float* __restrict__ W,
                                                 float* __restrict__ C)
{
    __shared__ float sA[64][36];
    __shared__ float sW[32][132];
    const int tid = threadIdx.x;
    const int tx = tid & 15, ty = tid >> 4;
    const int r0 = blockIdx.x * 64;

    float acc[4][8];
#pragma unroll
    for (int r = 0; r < 4; r++)
#pragma unroll
        for (int c = 0; c < 8; c++) acc[r][c] = 0.f;

    for (int kk = 0; kk < DM; kk += 32) {
        for (int t = tid; t < 64 * 32; t += 256) {
            int r = t >> 5, i = t & 31;
            sA[r][i] = A[(size_t)(r0 + r) * DM + kk + i];
        }
        for (int t = tid; t < 32 * 128; t += 256) {
            int i = t >> 7, c = t & 127;
            sW[i][c] = W[(size_t)(kk + i) * DM + c];
        }
        __syncthreads();
#pragma unroll
        for (int i = 0; i < 32; i++) {
            float a[4];
#pragma unroll
            for (int r = 0; r < 4; r++) a[r] = sA[ty * 4 + r][i];
            float4 w0 = *(const float4*)&sW[i][tx * 8];
            float4 w1 = *(const float4*)&sW[i][tx * 8 + 4];
            float w[8] = {w0.x, w0.y, w0.z, w0.w, w1.x, w1.y, w1.z, w1.w};
#pragma unroll
            for (int r = 0; r < 4; r++)
#pragma unroll
                for (int c = 0; c < 8; c++) acc[r][c] += a[r] * w[c];
        }
        __syncthreads();
    }
#pragma unroll
    for (int r = 0; r < 4; r++) {
        size_t row = (size_t)(r0 + ty * 4 + r);
        float4 o0 = make_float4(acc[r][0], acc[r][1], acc[r][2], acc[r][3]);
        float4 o1 = make_float4(acc[r][4], acc[r][5], acc[r][6], acc[r][7]);
        *(float4*)&C[row * DM + tx * 8]     = o0;
        *(float4*)&C[row * DM + tx * 8 + 4] = o1;
    }
}

// ---------------------------------------------------------------------------
// K2: single-pass attention. Per (b,h,q-tile): scores -> exp (unnormalized)
// -> write attn + accumulate rowsum + context. Context normalized at end.
// ---------------------------------------------------------------------------
__global__ __launch_bounds__(256) void attn_pass(const unsigned char* __restrict__ mask,
                                                 float* __restrict__ attn)
{
    extern __shared__ float sm[];
    float* sQt = sm + SQT_OFF;   // [32][132]  (d-major, q inner)
    float* sKt = sm + SKT_OFF;   // [32][68]
    float* sVt = sm + SVT_OFF;   // [32][68]
    float* sS  = sm + SS_OFF;    // [128][68]
    __shared__ float srinv[128];

    const int tid = threadIdx.x;
    const int tx = tid & 15, ty = tid >> 4;
    const int bh = blockIdx.y;
    const int b = bh >> 2, h = bh & 3;
    const int q0 = blockIdx.x * TQ;
    const float scale = 0.17677669529663689f;  // 1/sqrt(32)
    const int mmode = g_mask_mode;

    // load + transpose Q tile [128 q][32 d] -> sQt[d][q]
    const float* Qb = g_Qp + ((size_t)(b * SEQ + q0)) * DM + h * DKC;
    for (int t = tid; t < TQ * DKC; t += 256) {
        int q = t >> 5, d = t & 31;
        sQt[d * 132 + q] = Qb[(size_t)q * DM + d];
    }
    __syncthreads();

    float rowsum[8];
    float cacc[8][2];
#pragma unroll
    for (int a = 0; a < 8; a++) { rowsum[a] = 0.f; cacc[a][0] = 0.f; cacc[a][1] = 0.f; }

    for (int kc = 0; kc < SEQ / TK; kc++) {
        const int k0 = kc * TK;
        const float* Kb = g_Kp + ((size_t)(b * SEQ + k0)) * DM + h * DKC;
        const float* Vb = g_Vp + ((size_t)(b * SEQ + k0)) * DM + h * DKC;
        for (int t = tid; t < TK * DKC; t += 256) {
            int k = t >> 5, d = t & 31;
            sKt[d * 68 + k] = Kb[(size_t)k * DM + d];
            sVt[d * 68 + k] = Vb[(size_t)k * DM + d];
        }
        __syncthreads();

        // scores: 8q x 4k per thread, tile 128x64
        float acc[8][4];
#pragma unroll
        for (int a = 0; a < 8; a++)
#pragma unroll
            for (int c = 0; c < 4; c++) acc[a][c] = 0.f;

#pragma unroll 8
        for (int i = 0; i < DKC; i++) {
            float4 qa = *(const float4*)&sQt[i * 132 + ty * 8];
            float4 qb2 = *(const float4*)&sQt[i * 132 + ty * 8 + 4];
            float4 kv = *(const float4*)&sKt[i * 68 + tx * 4];
            float qs[8] = {qa.x, qa.y, qa.z, qa.w, qb2.x, qb2.y, qb2.z, qb2.w};
            float ks[4] = {kv.x, kv.y, kv.z, kv.w};
#pragma unroll
            for (int a = 0; a < 8; a++)
#pragma unroll
                for (int c = 0; c < 4; c++) acc[a][c] += qs[a] * ks[c];
        }

        // exp + mask + store (unnormalized) to gmem + smem
#pragma unroll
        for (int a = 0; a < 8; a++) {
            const int q = q0 + ty * 8 + a;
            uint4 m4 = load_mask4(mask, ((size_t)b * SEQ + q) * SEQ + k0 + tx * 4, mmode);
            float e0 = m4.x ? 0.f : __expf(acc[a][0] * scale);
            float e1 = m4.y ? 0.f : __expf(acc[a][1] * scale);
            float e2 = m4.z ? 0.f : __expf(acc[a][2] * scale);
            float e3 = m4.w ? 0.f : __expf(acc[a][3] * scale);
            rowsum[a] += (e0 + e1) + (e2 + e3);
            float4 ev = make_float4(e0, e1, e2, e3);
            *(float4*)&sS[(ty * 8 + a) * 68 + tx * 4] = ev;
            *(float4*)(attn + (((size_t)bh * SEQ + q) * SEQ + k0 + tx * 4)) = ev;
        }
        __syncthreads();

        // context: 8q x 2d per thread (d = tx, tx+16), over 64 k
#pragma unroll 4
        for (int kk = 0; kk < TK; kk += 4) {
            float4 v0 = *(const float4*)&sVt[tx * 68 + kk];
            float4 v1 = *(const float4*)&sVt[(tx + 16) * 68 + kk];
#pragma unroll
            for (int a = 0; a < 8; a++) {
                float4 s4 = *(const float4*)&sS[(ty * 8 + a) * 68 + kk];
                cacc[a][0] += s4.x * v0.x; cacc[a][0] += s4.y * v0.y;
                cacc[a][0] += s4.z * v0.z; cacc[a][0] += s4.w * v0.w;
                cacc[a][1] += s4.x * v1.x; cacc[a][1] += s4.y * v1.y;
                cacc[a][1] += s4.z * v1.z; cacc[a][1] += s4.w * v1.w;
            }
        }
        __syncthreads();
    }

    // rowsum reduction across 16 tx lanes (reuse sS)
    float* red = sS;
#pragma unroll
    for (int a = 0; a < 8; a++) red[(ty * 8 + a) * 17 + tx] = rowsum[a];
    __syncthreads();
    if (tid < 128) {
        float s = 0.f;
#pragma unroll
        for (int j = 0; j < 16; j++) s += red[tid * 17 + j];
        float r = 1.0f / s;
        srinv[tid] = r;
        g_rinv[(size_t)bh * SEQ + q0 + tid] = r;
    }
    __syncthreads();

#pragma unroll
    for (int a = 0; a < 8; a++) {
        float r = srinv[ty * 8 + a];
        size_t o = ((size_t)(b * SEQ + q0 + ty * 8 + a)) * DM + h * DKC;
        g_ctx[o + tx]      = cacc[a][0] * r;
        g_ctx[o + tx + 16] = cacc[a][1] * r;
    }
}

// ---------------------------------------------------------------------------
// K3: attn *= rinv[row]   (1.07 GB streamed, float4)
// ---------------------------------------------------------------------------
__global__ void norm_attn(float* __restrict__ attn)
{
    size_t i = (size_t)blockIdx.x * blockDim.x + threadIdx.x;  // one float4 each
    size_t row = i >> 9;                                       // 512 float4 per row
    float r = __ldg(&g_rinv[row]);
    float4* p = (float4*)attn;
    float4 v = p[i];
    v.x *= r; v.y *= r; v.z *= r; v.w *= r;
    p[i] = v;
}

// ---------------------------------------------------------------------------
// K4: out = LayerNorm(g_ctx @ W_fc + g_R) * gamma + beta
// ---------------------------------------------------------------------------
__global__ __launch_bounds__(256) void out_ln(const float* __restrict__ Wfc,
                                              const float* __restrict__ gamma,
                                              const float* __restrict__ beta,
                                              float* __restrict__ out)
{
    __shared__ float sA[64][36];
    __shared__ float sW[32][132];
    __shared__ float red1[64][17];
    __shared__ float red2[64][17];
    __shared__ float smu[64];
    __shared__ float srs[64];

    const int tid = threadIdx.x;
    const int tx = tid & 15, ty = tid >> 4;
    const int r0 = blockIdx.x * 64;

    float acc[4][8];
#pragma unroll
    for (int r = 0; r < 4; r++)
#pragma unroll
        for (int c = 0; c < 8; c++) acc[r][c] = 0.f;

    for (int kk = 0; kk < DM; kk += 32) {
        for (int t = tid; t < 64 * 32; t += 256) {
            int r = t >> 5, i = t & 31;
            sA[r][i] = g_ctx[(size_t)(r0 + r) * DM + kk + i];
        }
        for (int t = tid; t < 32 * 128; t += 256) {
            int i = t >> 7, c = t & 127;
            sW[i][c] = Wfc[(size_t)(kk + i) * DM + c];
        }
        __syncthreads();
#pragma unroll
        for (int i = 0; i < 32; i++) {
            float a[4];
#pragma unroll
            for (int r = 0; r < 4; r++) a[r] = sA[ty * 4 + r][i];
            float4 w0 = *(const float4*)&sW[i][tx * 8];
            float4 w1 = *(const float4*)&sW[i][tx * 8 + 4];
            float w[8] = {w0.x, w0.y, w0.z, w0.w, w1.x, w1.y, w1.z, w1.w};
#pragma unroll
            for (int r = 0; r < 4; r++)
#pragma unroll
                for (int c = 0; c < 8; c++) acc[r][c] += a[r] * w[c];
        }
        __syncthreads();
    }

    // add residual, per-row partial moments
#pragma unroll
    for (int r = 0; r < 4; r++) {
        size_t row = (size_t)(r0 + ty * 4 + r);
        float4 rv0 = *(const float4*)&g_R[row * DM + tx * 8];
        float4 rv1 = *(const float4*)&g_R[row * DM + tx * 8 + 4];
        float rs[8] = {rv0.x, rv0.y, rv0.z, rv0.w, rv1.x, rv1.y, rv1.z, rv1.w};
        float ps = 0.f, pq = 0.f;
#pragma unroll
        for (int c = 0; c < 8; c++) {
            acc[r][c] += rs[c];
            ps += acc[r][c];
            pq += acc[r][c] * acc[r][c];
        }
        red1[ty * 4 + r][tx] = ps;
        red2[ty * 4 + r][tx] = pq;
    }
    __syncthreads();
    if (tid < 64) {
        float s = 0.f, q = 0.f;
#pragma unroll
        for (int j = 0; j < 16; j++) { s += red1[tid][j]; q += red2[tid][j]; }
        float mu = s * (1.0f / 128.0f);
        float var = q * (1.0f / 128.0f) - mu * mu;
        smu[tid] = mu;
        srs[tid] = rsqrtf(var + 1e-5f);
    }
    __syncthreads();

    float4 g0 = *(const float4*)&gamma[tx * 8];
    float4 g1 = *(const float4*)&gamma[tx * 8 + 4];
    float4 b0 = *(const float4*)&beta[tx * 8];
    float4 b1 = *(const float4*)&beta[tx * 8 + 4];
    float gs[8] = {g0.x, g0.y, g0.z, g0.w, g1.x, g1.y, g1.z, g1.w};
    float bs[8] = {b0.x, b0.y, b0.z, b0.w, b1.x, b1.y, b1.z, b1.w};

#pragma unroll
    for (int r = 0; r < 4; r++) {
        float mu = smu[ty * 4 + r];
        float rstd = srs[ty * 4 + r];
        size_t row = (size_t)(r0 + ty * 4 + r);
        float o[8];
#pragma unroll
        for (int c = 0; c < 8; c++) o[c] = (acc[r][c] - mu) * rstd * gs[c] + bs[c];
        *(float4*)&out[row * DM + tx * 8]     = make_float4(o[0], o[1], o[2], o[3]);
        *(float4*)&out[row * DM + tx * 8 + 4] = make_float4(o[4], o[5], o[6], o[7]);
    }
}

// ---------------------------------------------------------------------------
extern "C" void kernel_launch(void* const* d_in, const int* in_sizes, int n_in,
                              void* d_out, int out_size)
{
    const float* inQ  = (const float*)d_in[0];
    const float* inK  = (const float*)d_in[1];
    const float* inV  = (const float*)d_in[2];
    const unsigned char* mask = (const unsigned char*)d_in[3];
    const float* Wfc0 = (const float*)d_in[4];
    const float* WQ   = (const float*)d_in[5];
    const float* WK   = (const float*)d_in[6];
    const float* WV   = (const float*)d_in[7];
    const float* Wfc  = (const float*)d_in[8];
    const float* gam  = (const float*)d_in[9];
    const float* bet  = (const float*)d_in[10];
    float* out  = (float*)d_out;
    float* attn = out + OUT_ELEMS;

    void *pR, *pQ, *pK, *pV;
    cudaGetSymbolAddress(&pR, g_R);
    cudaGetSymbolAddress(&pQ, g_Qp);
    cudaGetSymbolAddress(&pK, g_Kp);
    cudaGetSymbolAddress(&pV, g_Vp);

    // K0: mask dtype detection
    detect_mask<<<1, 256>>>(mask);

    // K1: projections
    gemm_proj<<<NR / 64, 256>>>(inQ, Wfc0, (float*)pR);
    gemm_proj<<<NR / 64, 256>>>(inQ, WQ,   (float*)pQ);
    gemm_proj<<<NR / 64, 256>>>(inK, WK,   (float*)pK);
    gemm_proj<<<NR / 64, 256>>>(inV, WV,   (float*)pV);

    // K2: attention (unnormalized attn write + context)
    cudaFuncSetAttribute(attn_pass, cudaFuncAttributeMaxDynamicSharedMemorySize,
                         (int)SMEM_BYTES);
    dim3 agrid(SEQ / TQ, BATCH * NH);
    attn_pass<<<agrid, 256, SMEM_BYTES>>>(mask, attn);

    // K3: normalize attn in place
    size_t nf4 = (size_t)BATCH * NH * SEQ * SEQ / 4;   // 33,554,432
    norm_attn<<<(unsigned)(nf4 / 256), 256>>>(attn);

    // K4: output projection + residual + LayerNorm
    out_ln<<<NR / 64, 256>>>(Wfc, gam, bet, out);
}